// round 1
// baseline (speedup 1.0000x reference)
#include <cuda_runtime.h>
#include <cuda_bf16.h>
#include <math.h>

// Problem constants (fixed by reference)
#define B_      16
#define T_      8192
#define D_      512
#define H_      8
#define HD_     64
#define K_      4
#define SPLITS_ 32
#define CHUNK_  (T_/SPLITS_)      // 256
#define TROWS_  32
#define NTILES_ (CHUNK_/TROWS_)   // 8
#define TSTRIDE_ 516              // 512 + 4 pad: conflict-free LDS.128 columns
#define NTHR_   256

#define SM_TILE_F (TROWS_*TSTRIDE_)   // 16512
#define SM_Q_F    (K_*D_)             // 2048
#define SM_P_F    (H_*TROWS_*K_)      // 1024
#define SMEM_BYTES ((SM_TILE_F + SM_Q_F + SM_P_F + TROWS_)*4)  // 78464

// ---------------- device scratch (no allocations allowed) ----------------
__device__ __align__(16) float g_m  [B_*SPLITS_*H_*K_];
__device__ __align__(16) float g_l  [B_*SPLITS_*H_*K_];
__device__ __align__(16) float g_acc[B_*SPLITS_*H_*K_*HD_];
__device__ __align__(16) float g_pool[B_*K_*D_];

// ---------------- packed fp32x2 FMA (Blackwell) ----------------
union F2U { float2 f; unsigned long long u; };
__device__ __forceinline__ float2 ffma2(float2 a, float2 b, float2 c) {
    F2U A, Bv, C, Dv;
    A.f = a; Bv.f = b; C.f = c;
    asm("fma.rn.f32x2 %0, %1, %2, %3;" : "=l"(Dv.u) : "l"(A.u), "l"(Bv.u), "l"(C.u));
    return Dv.f;
}

// ======================================================================
// Kernel 1: streaming online-softmax attention pooling, per (batch, split)
// ======================================================================
__global__ void __launch_bounds__(NTHR_, 2)
attn_main(const float* __restrict__ x, const int* __restrict__ mask,
          const float* __restrict__ queries)
{
    extern __shared__ float sm[];
    float* tile = sm;                       // [TROWS_][TSTRIDE_]
    float* q_sh = sm + SM_TILE_F;           // [K_][D_]
    float* p_sh = q_sh + SM_Q_F;            // [H_][TROWS_][K_]
    int*   msk  = (int*)(p_sh + SM_P_F);    // [TROWS_]

    const int b    = blockIdx.x / SPLITS_;
    const int s    = blockIdx.x % SPLITS_;
    const int tid  = threadIdx.x;
    const int w    = tid >> 5;              // warp == head
    const int lane = tid & 31;

    // load queries into shared once (2048 floats)
    #pragma unroll
    for (int i = tid; i < SM_Q_F/4; i += NTHR_) {
        *reinterpret_cast<float4*>(q_sh + i*4) =
            *reinterpret_cast<const float4*>(queries + i*4);
    }

    float  m[K_], l[K_];
    float2 acc[K_];
    #pragma unroll
    for (int k = 0; k < K_; k++) {
        m[k] = -3.0e38f; l[k] = 0.f; acc[k] = make_float2(0.f, 0.f);
    }

    const float* xb = x + (long)b * T_ * D_;
    const int*   mb = mask + (long)b * T_;
    const int    t_base = s * CHUNK_;

    for (int tl = 0; tl < NTILES_; tl++) {
        const int t0 = t_base + tl * TROWS_;

        // ---- cooperative tile load: 32 rows x 512 floats (coalesced) ----
        #pragma unroll
        for (int it = 0; it < 16; it++) {
            int f   = tid + NTHR_ * it;     // 0..4095
            int row = f >> 7;               // /128
            int c4  = f & 127;
            float4 v = *reinterpret_cast<const float4*>(
                           xb + (long)(t0 + row) * D_ + c4 * 4);
            *reinterpret_cast<float4*>(tile + row * TSTRIDE_ + c4 * 4) = v;
        }
        if (tid < TROWS_) msk[tid] = mb[t0 + tid];
        __syncthreads();

        // ---- phase 1: lane = t, compute 4 scores via packed FMA ----
        float2 sk[K_];
        #pragma unroll
        for (int k = 0; k < K_; k++) sk[k] = make_float2(0.f, 0.f);
        const float* vrow = tile + lane * TSTRIDE_ + w * HD_;
        const float* qh   = q_sh + w * HD_;
        #pragma unroll
        for (int i4 = 0; i4 < 16; i4++) {
            float4 v4 = *reinterpret_cast<const float4*>(vrow + i4 * 4);
            float2 va = make_float2(v4.x, v4.y);
            float2 vb = make_float2(v4.z, v4.w);
            #pragma unroll
            for (int k = 0; k < K_; k++) {
                float4 q4 = *reinterpret_cast<const float4*>(qh + k * D_ + i4 * 4);
                sk[k] = ffma2(va, make_float2(q4.x, q4.y), sk[k]);
                sk[k] = ffma2(vb, make_float2(q4.z, q4.w), sk[k]);
            }
        }
        const int mv = msk[lane];
        float sc[K_];
        #pragma unroll
        for (int k = 0; k < K_; k++) {
            sc[k] = (sk[k].x + sk[k].y) * 0.125f;   // / sqrt(64)
            if (mv == 0) sc[k] = -1.0e9f;           // exact reference semantics
        }
        // online softmax update (warp-uniform m, l)
        float alpha[K_], p[K_];
        #pragma unroll
        for (int k = 0; k < K_; k++) {
            float v = sc[k];
            #pragma unroll
            for (int off = 16; off > 0; off >>= 1)
                v = fmaxf(v, __shfl_xor_sync(0xffffffffu, v, off));
            float mn = fmaxf(m[k], v);
            alpha[k] = __expf(m[k] - mn);
            m[k] = mn;
            p[k] = __expf(sc[k] - mn);
            float psum = p[k];
            #pragma unroll
            for (int off = 16; off > 0; off >>= 1)
                psum += __shfl_xor_sync(0xffffffffu, psum, off);
            l[k] = l[k] * alpha[k] + psum;
        }
        // stash p (float4 per lane, conflict-free STS.128)
        *reinterpret_cast<float4*>(p_sh + (w * TROWS_ + lane) * K_) =
            make_float4(p[0], p[1], p[2], p[3]);
        __syncwarp();

        // ---- phase 2: lane owns d = {2*lane, 2*lane+1} of this head ----
        #pragma unroll
        for (int k = 0; k < K_; k++) { acc[k].x *= alpha[k]; acc[k].y *= alpha[k]; }
        const float* base2 = tile + w * HD_ + 2 * lane;
        const float* pb    = p_sh + w * TROWS_ * K_;
        #pragma unroll 8
        for (int t = 0; t < TROWS_; t++) {
            float2 v2 = *reinterpret_cast<const float2*>(base2 + t * TSTRIDE_);
            float4 p4 = *reinterpret_cast<const float4*>(pb + t * K_);
            acc[0] = ffma2(v2, make_float2(p4.x, p4.x), acc[0]);
            acc[1] = ffma2(v2, make_float2(p4.y, p4.y), acc[1]);
            acc[2] = ffma2(v2, make_float2(p4.z, p4.z), acc[2]);
            acc[3] = ffma2(v2, make_float2(p4.w, p4.w), acc[3]);
        }
        __syncthreads();   // protect tile/p_sh before next load
    }

    // ---- write split partials ----
    const long idxBase = (((long)b * SPLITS_ + s) * H_ + w) * K_;
    if (lane == 0) {
        #pragma unroll
        for (int k = 0; k < K_; k++) { g_m[idxBase + k] = m[k]; g_l[idxBase + k] = l[k]; }
    }
    #pragma unroll
    for (int k = 0; k < K_; k++) {
        *reinterpret_cast<float2*>(&g_acc[(idxBase + k) * HD_ + 2 * lane]) = acc[k];
    }
}

// ======================================================================
// Kernel 2: merge split partials -> pooled[b,k,h*64+d]
// ======================================================================
__global__ void combine_k()
{
    const int idx = blockIdx.x;             // b*H*K + h*K + k
    const int k = idx % K_;
    const int h = (idx / K_) % H_;
    const int b = idx / (K_ * H_);
    const int d = threadIdx.x;              // 0..63

    float mt = -3.0e38f;
    #pragma unroll
    for (int s = 0; s < SPLITS_; s++)
        mt = fmaxf(mt, g_m[(((long)b * SPLITS_ + s) * H_ + h) * K_ + k]);

    float lt = 0.f, a = 0.f;
    #pragma unroll
    for (int s = 0; s < SPLITS_; s++) {
        long p = (((long)b * SPLITS_ + s) * H_ + h) * K_ + k;
        float scl = __expf(g_m[p] - mt);
        lt += g_l[p] * scl;
        a  += g_acc[p * HD_ + d] * scl;
    }
    g_pool[((long)b * K_ + k) * D_ + h * HD_ + d] = a / lt;
}

// ======================================================================
// Kernel 3: out[row, j] = b_out[j] + sum_i pooled[row, i] * w_out[j, i]
// ======================================================================
__global__ void linear_k(const float* __restrict__ w_out,
                         const float* __restrict__ b_out,
                         float* __restrict__ out)
{
    __shared__ __align__(16) float ps[D_];
    const int row = blockIdx.x;             // 0..63 (= b*K + k)
    const int jt  = blockIdx.y;             // 0..3
    const int tid = threadIdx.x;            // 128

    for (int i = tid; i < D_; i += 128) ps[i] = g_pool[(long)row * D_ + i];
    __syncthreads();

    const int j = jt * 128 + tid;
    const float* wr = w_out + (long)j * D_;
    float2 a2 = make_float2(0.f, 0.f);
    #pragma unroll 4
    for (int i4 = 0; i4 < D_/4; i4++) {
        float4 wv = *reinterpret_cast<const float4*>(wr + i4 * 4);
        float4 pv = *reinterpret_cast<const float4*>(&ps[i4 * 4]);
        a2 = ffma2(make_float2(wv.x, wv.y), make_float2(pv.x, pv.y), a2);
        a2 = ffma2(make_float2(wv.z, wv.w), make_float2(pv.z, pv.w), a2);
    }
    out[(long)row * D_ + j] = b_out[j] + a2.x + a2.y;
}

// ======================================================================
extern "C" void kernel_launch(void* const* d_in, const int* in_sizes, int n_in,
                              void* d_out, int out_size)
{
    const float* x       = (const float*)d_in[0];
    const int*   mask    = (const int*)  d_in[1];
    const float* queries = (const float*)d_in[2];
    const float* w_out   = (const float*)d_in[3];
    const float* b_out   = (const float*)d_in[4];
    float* out = (float*)d_out;

    cudaFuncSetAttribute((const void*)attn_main,
                         cudaFuncAttributeMaxDynamicSharedMemorySize, SMEM_BYTES);

    attn_main<<<B_ * SPLITS_, NTHR_, SMEM_BYTES>>>(x, mask, queries);
    combine_k<<<B_ * H_ * K_, HD_>>>();
    linear_k<<<dim3(B_ * K_, D_ / 128), 128>>>(w_out, b_out, out);
}